// round 17
// baseline (speedup 1.0000x reference)
#include <cuda_runtime.h>

#define TPB 256
#define F4_PER_BLOCK 1664   // 256 cells * 26 floats / 4 = 128 * 13 (13-periodic, block-aligned)

__device__ __forceinline__ float compute_iou(float bx, float by, float bw, float bh,
                                             float lx, float ly, float lw, float lh) {
    const float invS = 1.0f / 7.0f;
    float x1 = bx * invS - bw * 0.5f;
    float y1 = by * invS - bh * 0.5f;
    float x2 = bx * invS + bw * 0.5f;
    float y2 = by * invS + bh * 0.5f;
    float u1 = lx * invS - lw * 0.5f;
    float v1 = ly * invS - lh * 0.5f;
    float u2 = lx * invS + lw * 0.5f;
    float v2 = ly * invS + lh * 0.5f;
    float a1 = (x2 - x1) * (y2 - y1);
    float a2 = (u2 - u1) * (v2 - v1);
    float left   = fmaxf(x1, u1);
    float right  = fminf(x2, u2);
    float top    = fmaxf(y1, v1);
    float bottom = fminf(y2, v2);
    bool valid = (left < right) && (top < bottom);
    float inter = valid ? (right - left) * (bottom - top) : 0.0f;
    float uni = a1 + a2 - inter;
    return valid ? (inter / uni) : 0.0f;
}

// Cold path (~4% of cells). Returns the coord-cell loss terms MINUS the
// 0.5*(p4^2+p9^2) that the unmasked conf stream has already added.
__device__ __noinline__ float coord_cell_extra(const float* __restrict__ pbase,
                                               const float* __restrict__ lbase) {
    const float2* pp = reinterpret_cast<const float2*>(pbase);
    const float2* lp = reinterpret_cast<const float2*>(lbase);

    float2 p01 = __ldg(pp + 0);
    float2 p23 = __ldg(pp + 1);
    float2 p45 = __ldg(pp + 2);
    float2 p67 = __ldg(pp + 3);
    float2 p89 = __ldg(pp + 4);
    float2 l01 = __ldg(lp + 0);
    float2 l23 = __ldg(lp + 1);

    float cls = 0.0f;
#pragma unroll
    for (int j = 5; j < 13; j++) {
        float2 pv = __ldg(pp + j);
        float2 lv = __ldg(lp + j);
        float dx = pv.x - lv.x;
        float dy = pv.y - lv.y;
        cls += dx * dx + dy * dy;
    }

    float iou1 = compute_iou(p01.x, p01.y, p23.x, p23.y,
                             l01.x, l01.y, l23.x, l23.y);
    float iou2 = compute_iou(p45.y, p67.x, p67.y, p89.x,
                             l01.x, l01.y, l23.x, l23.y);
    bool pick1 = iou1 > iou2;

    float s0 = pick1 ? p01.x : p45.y;
    float s1 = pick1 ? p01.y : p67.x;
    float s2 = pick1 ? p23.x : p67.y;
    float s3 = pick1 ? p23.y : p89.x;

    float d0 = s0 - l01.x;
    float d1 = s1 - l01.y;
    float d2 = sqrtf(s2) - sqrtf(l23.x);
    float d3 = sqrtf(s3) - sqrtf(l23.y);
    float coord_cell = d0 * d0 + d1 * d1 + d2 * d2 + d3 * d3;

    float p4 = p45.x, p9 = p89.y;
    float c  = pick1 ? p4 : p9;
    float io = pick1 ? iou1 : iou2;
    float dc = c - io;
    float obj_c_cell = dc * dc;

    float other = pick1 ? p9 : p4;

    // full coord-cell terms minus the stream's 0.5*(p4^2 + p9^2)
    return 5.0f * coord_cell + obj_c_cell + cls
           + 0.5f * (other * other - p4 * p4 - p9 * p9);
}

__global__ void __launch_bounds__(TPB)
yolo_kernel(const float* __restrict__ predict,
            const float* __restrict__ label,
            int ncells, int rem, float invN,
            float* __restrict__ out) {
    const int tid = threadIdx.x;
    const int cell = blockIdx.x * TPB + tid;
    const long long nf4 = ((long long)ncells * 26) >> 2;  // floor; rem floats handled below
    const long long base_f4 = (long long)blockIdx.x * F4_PER_BLOCK;
    const float4* P4 = reinterpret_cast<const float4*>(predict);

    float loss = 0.0f;

    // ---- scattered part: label l4 only; coord handler for ~4% ----
    if (cell < ncells) {
        float l4 = __ldg(label + (size_t)cell * 26 + 4);
        if (l4 > 0.0f)
            loss = coord_cell_extra(predict + (size_t)cell * 26,
                                    label   + (size_t)cell * 26);
    }

    // ---- coalesced unmasked conf-square stream over predict ----
    // Block region is 13-periodic (1664 = 128*13): local f4 index i has
    // m = i % 13; conf slots: m==1 -> .x (p4), m==2 -> .y (p9),
    // m==7 -> .z (p4), m==8 -> .w (p9).
#pragma unroll
    for (int k = 0; k < 7; k++) {
        int i = tid + k * TPB;
        long long gi = base_f4 + i;
        if (i < F4_PER_BLOCK && gi < nf4) {
            float4 v = __ldg(P4 + gi);
            unsigned q = (unsigned)i / 13u;       // multiply-shift
            unsigned m = (unsigned)i - 13u * q;
            if (m == 1u)      loss += 0.5f * v.x * v.x;
            else if (m == 2u) loss += 0.5f * v.y * v.y;
            else if (m == 7u) loss += 0.5f * v.z * v.z;
            else if (m == 8u) loss += 0.5f * v.w * v.w;
        }
    }

    // ---- scalar remainder (total floats not divisible by 4; insurance) ----
    if (rem > 0 && blockIdx.x == 0 && tid == 0) {
        long long p0 = nf4 << 2;
        for (int j = 0; j < rem; j++) {
            long long pos = p0 + j;
            unsigned c = (unsigned)(pos / 26);
            unsigned r = (unsigned)(pos - 26ll * c);
            if (r == 4u || r == 9u) {
                float f = __ldg(predict + pos);
                loss += 0.5f * f * f;
            }
        }
    }

    // ---- block reduction ----
    __shared__ float sm[TPB / 32];
    float s = loss;
#pragma unroll
    for (int o = 16; o > 0; o >>= 1)
        s += __shfl_down_sync(0xFFFFFFFFu, s, o);
    if ((tid & 31) == 0)
        sm[tid >> 5] = s;
    __syncthreads();
    if (tid < 32) {
        s = (tid < (TPB / 32)) ? sm[tid] : 0.0f;
#pragma unroll
        for (int o = 16; o > 0; o >>= 1)
            s += __shfl_down_sync(0xFFFFFFFFu, s, o);
        if (tid == 0) {
            // Fire-and-forget no-return reduction into pre-zeroed out[0].
            float contrib = s * invN;
            asm volatile("red.relaxed.gpu.global.add.f32 [%0], %1;"
                         :: "l"(out), "f"(contrib) : "memory");
        }
    }
}

extern "C" void kernel_launch(void* const* d_in, const int* in_sizes, int n_in,
                              void* d_out, int out_size) {
    const float* predict = (const float*)d_in[0];
    const float* label   = (const float*)d_in[1];
    float* out = (float*)d_out;

    int total  = in_sizes[0];          // B*7*7*26 floats
    int ncells = total / 26;           // B*49
    int rem    = total & 3;            // floats beyond the float4 part
    int nblocks = (ncells + TPB - 1) / TPB;

    float invN = 49.0f / (float)ncells;  // 1 / batch

    cudaMemsetAsync(d_out, 0, sizeof(float), 0);
    yolo_kernel<<<nblocks, TPB>>>(predict, label, ncells, rem, invN, out);
}